// round 4
// baseline (speedup 1.0000x reference)
#include <cuda_runtime.h>
#include <cuda_bf16.h>

// SimplePatchScorer: x (512,3,224,224) f32, W (1,768) f32, b (1,) f32
// out (512,196) f32.
//
// Index algebra: f' = t*588 + e, t = i*16+j, e = c*196+hn*14+wn.
// row r = f'/768, weight col k = f' mod 768.
//  (1) Δi=4 -> Δf' = 37632 = 49*768: same k, row +49. One weight load
//      feeds 4 FMAs (rows i = im, im+4, im+8, im+12).
//  (2) Each thread streams the FULL e = 0..587 (single lockstep frontier
//      per image -> 16 contiguous row-streams/image = DRAM-row friendly,
//      the ordering that measured 100% DRAM efficiency in R2).
//  (3) k wraps 768 at most once over 588 steps -> two-pass loop, register
//      accumulation, <=8 shared atomics per thread.
//  (4) Weights in smem, swizzled idx = k + (k>>5): conflict-free.

#define BATCH   512
#define CIMG    3
#define HW      224
#define PATCH   16
#define NPATCH  14
#define NROWS   196
#define KLEN    768
#define ELEN    588
#define IMG_ELEMS (CIMG*HW*HW)   // 150528
#define ROW_STRIDE (PATCH*HW)    // 3584
#define SWSZ    792              // 768 + 768/32 swizzle padding

#define IMGS_PER_CTA 2
#define TPB          128         // 64 threads per image

__global__ __launch_bounds__(TPB, 8)
void patch_scorer_kernel(const float* __restrict__ x,
                         const float* __restrict__ W,
                         const float* __restrict__ bias,
                         float* __restrict__ out)
{
    __shared__ float sWs[SWSZ];                  // swizzled weights
    __shared__ float sAcc[IMGS_PER_CTA][NROWS];

    const int tid = threadIdx.x;
    const int sub = tid >> 6;                    // image slot 0/1
    const int st  = tid & 63;                    // thread within image
    const int b   = blockIdx.x * IMGS_PER_CTA + sub;

    // stage swizzled weights + zero accumulators
    #pragma unroll
    for (int k = tid; k < KLEN; k += TPB)
        sWs[k + (k >> 5)] = W[k];
    #pragma unroll
    for (int i = tid; i < IMGS_PER_CTA * NROWS; i += TPB)
        (&sAcc[0][0])[i] = 0.0f;
    __syncthreads();

    const int im = st >> 4;                      // i mod 4
    const int j  = st & 15;                      // patch column

    const int t0   = im * 16 + j;
    const int base = t0 * ELEN;
    const int r0   = base / KLEN;                // base output row (0..48)
    const int k0   = base - r0 * KLEN;           // starting weight column
    const int n1   = (KLEN - k0 < ELEN) ? (KLEN - k0) : ELEN;

    // stream start: e=0 -> c=0, hn=0, wn=0, off=0
    const float* px = x + (size_t)b * IMG_ELEMS + im * HW + j;

    float a0 = 0.f, a1 = 0.f, a2 = 0.f, a3 = 0.f;
    int off = 0, wn = 0, k = k0, n = 0;

    #pragma unroll 4
    for (; n < n1; ++n) {
        const float w = sWs[k + (k >> 5)];
        const float* p = px + off;
        a0 += p[0]        * w;
        a1 += p[4  * HW]  * w;
        a2 += p[8  * HW]  * w;
        a3 += p[12 * HW]  * w;
        ++k;
        off += PATCH;
        if (++wn == NPATCH) { wn = 0; off += ROW_STRIDE - NPATCH * PATCH; }
    }

    atomicAdd(&sAcc[sub][r0      ], a0);
    atomicAdd(&sAcc[sub][r0 +  49], a1);
    atomicAdd(&sAcc[sub][r0 +  98], a2);
    atomicAdd(&sAcc[sub][r0 + 147], a3);

    if (n1 < ELEN) {                             // window wraps into next row
        k = 0;
        a0 = a1 = a2 = a3 = 0.f;
        #pragma unroll 4
        for (; n < ELEN; ++n) {
            const float w = sWs[k + (k >> 5)];
            const float* p = px + off;
            a0 += p[0]        * w;
            a1 += p[4  * HW]  * w;
            a2 += p[8  * HW]  * w;
            a3 += p[12 * HW]  * w;
            ++k;
            off += PATCH;
            if (++wn == NPATCH) { wn = 0; off += ROW_STRIDE - NPATCH * PATCH; }
        }
        atomicAdd(&sAcc[sub][r0 +   1], a0);
        atomicAdd(&sAcc[sub][r0 +  50], a1);
        atomicAdd(&sAcc[sub][r0 +  99], a2);
        atomicAdd(&sAcc[sub][r0 + 148], a3);
    }

    __syncthreads();

    const float bv = bias[0];
    #pragma unroll
    for (int idx = tid; idx < IMGS_PER_CTA * NROWS; idx += TPB) {
        const int s = (idx >= NROWS);
        const int r = idx - s * NROWS;
        out[(size_t)(blockIdx.x * IMGS_PER_CTA + s) * NROWS + r] = sAcc[s][r] + bv;
    }
}

extern "C" void kernel_launch(void* const* d_in, const int* in_sizes, int n_in,
                              void* d_out, int out_size)
{
    const float* x  = (const float*)d_in[0];   // (512,3,224,224)
    const float* W  = (const float*)d_in[1];   // (1,768)
    const float* bv = (const float*)d_in[2];   // (1,)
    float* out = (float*)d_out;                // (512,196)

    patch_scorer_kernel<<<BATCH / IMGS_PER_CTA, TPB>>>(x, W, bv, out);
}

// round 5
// speedup vs baseline: 1.2087x; 1.2087x over previous
#include <cuda_runtime.h>
#include <cuda_bf16.h>

// SimplePatchScorer: x (512,3,224,224) f32, W (1,768) f32, b (1,) f32
// out (512,196) f32.
//
// f' = t*588 + e, t = i*16+j, e = c*196+hn*14+wn; row = f'/768, k = f' mod 768.
//  (1) Δi=4 -> Δf' = 49*768: same k, row +49 -> one weight feeds 4 FMAs.
//  (2) Parity-split the e-stream: lane = (p = wn&1, j). e = p + 2n is LINEAR,
//      so k = k0 + 2n (wraps 768 at most once -> two-pass), and each warp
//      load covers cols 32s + 16p + j = one aligned 128B line. Wavefront-
//      optimal global traffic.
//  (3) Single lockstep frontier per image, 512 CTAs (full occupancy) -- the
//      combination R2 proved DRAM-efficient and R4 proved necessary.
//  (4) Weights swizzled in smem (idx = k + (k>>5)): conflict-free.

#define BATCH   512
#define CIMG    3
#define HW      224
#define PATCH   16
#define NPATCH  14
#define NROWS   196
#define KLEN    768
#define NITER   294              // 588/2 elements per parity stream
#define NBANDS  42               // 3c * 14hn
#define BAND_STRIDE 3584         // 16*224 floats per band
#define IMG_ELEMS (CIMG*HW*HW)   // 150528
#define SWSZ    792              // 768 + 768/32 swizzle padding
#define TPB     128

__global__ __launch_bounds__(TPB, 4)
void patch_scorer_kernel(const float* __restrict__ x,
                         const float* __restrict__ W,
                         const float* __restrict__ bias,
                         float* __restrict__ out)
{
    __shared__ float sWs[SWSZ];      // swizzled weights: sWs[k + (k>>5)] = W[k]
    __shared__ float sAcc[NROWS];

    const int tid = threadIdx.x;     // 128
    const int b   = blockIdx.x;      // image

    #pragma unroll
    for (int k = tid; k < KLEN; k += TPB)
        sWs[k + (k >> 5)] = W[k];
    #pragma unroll
    for (int r = tid; r < NROWS; r += TPB)
        sAcc[r] = 0.0f;
    __syncthreads();

    const int im   = tid >> 5;       // warp id = i mod 4
    const int lane = tid & 31;
    const int p    = lane >> 4;      // wn parity
    const int j    = lane & 15;      // patch column

    const int t0 = im * 16 + j;
    const int f0 = t0 * 588;
    const int r0 = f0 / KLEN;        // base output row (0..48)
    const int k0 = f0 - r0 * KLEN + p;
    int n1 = (KLEN - k0 + 1) >> 1;   // iters before k wraps 768
    if (n1 > NITER) n1 = NITER;

    // warp covers cols 32s + (16p + j): one aligned 128B line per load
    const float* px = x + (size_t)b * IMG_ELEMS + im * HW + p * PATCH + j;

    float a0 = 0.f, a1 = 0.f, a2 = 0.f, a3 = 0.f;
    int k = k0, off = 0, s = 0, n = 0;

    #pragma unroll 7
    for (; n < n1; ++n) {
        const float w = sWs[k + (k >> 5)];
        const float* q = px + off;
        a0 += q[0]        * w;       // row im
        a1 += q[4  * HW]  * w;       // row im+4
        a2 += q[8  * HW]  * w;       // row im+8
        a3 += q[12 * HW]  * w;       // row im+12
        k += 2;
        off += 32;
        if (++s == 7) { s = 0; off += BAND_STRIDE - 7 * 32; }
    }

    atomicAdd(&sAcc[r0      ], a0);
    atomicAdd(&sAcc[r0 +  49], a1);
    atomicAdd(&sAcc[r0 +  98], a2);
    atomicAdd(&sAcc[r0 + 147], a3);

    if (n1 < NITER) {                // stream wraps into next output row
        k -= KLEN;                   // k0 + 2*n1 - 768  (0 or 1)
        a0 = a1 = a2 = a3 = 0.f;
        #pragma unroll 7
        for (; n < NITER; ++n) {
            const float w = sWs[k + (k >> 5)];
            const float* q = px + off;
            a0 += q[0]        * w;
            a1 += q[4  * HW]  * w;
            a2 += q[8  * HW]  * w;
            a3 += q[12 * HW]  * w;
            k += 2;
            off += 32;
            if (++s == 7) { s = 0; off += BAND_STRIDE - 7 * 32; }
        }
        atomicAdd(&sAcc[r0 +   1], a0);
        atomicAdd(&sAcc[r0 +  50], a1);
        atomicAdd(&sAcc[r0 +  99], a2);
        atomicAdd(&sAcc[r0 + 148], a3);
    }

    __syncthreads();

    const float bv = bias[0];
    #pragma unroll
    for (int r = tid; r < NROWS; r += TPB)
        out[(size_t)b * NROWS + r] = sAcc[r] + bv;
}

extern "C" void kernel_launch(void* const* d_in, const int* in_sizes, int n_in,
                              void* d_out, int out_size)
{
    const float* x  = (const float*)d_in[0];   // (512,3,224,224)
    const float* W  = (const float*)d_in[1];   // (1,768)
    const float* bv = (const float*)d_in[2];   // (1,)
    float* out = (float*)d_out;                // (512,196)

    patch_scorer_kernel<<<BATCH, TPB>>>(x, W, bv, out);
}

// round 6
// speedup vs baseline: 2.6010x; 2.1519x over previous
#include <cuda_runtime.h>
#include <cuda_bf16.h>

// SimplePatchScorer: x (512,3,224,224) f32, W (1,768) f32, b (1,) f32
// out (512,196) f32.
//
// f' = t*588 + e, t = i*16+j, e = c*196+hn*14+wn; row = f'/768, k = f' mod 768.
//  (1) Δi=8 -> Δf' = 128*588 = 98*768 exactly: same k, row +98. One weight
//      feeds 2 FMAs (rows i = im, im+8). Relaxed from 4-way so each image
//      gets 2x the threads.
//  (2) 1024 CTAs x 256 threads = 8192 warps (measured law: delivered BW is
//      proportional to warps in flight; 4096 warps -> 2.25 TB/s).
//  (3) CTA = (image b, e-half g). e-half g starts at float offset g*75264
//      (e=294 -> c=1,hn=7,wn=0). Single clean frontier per CTA.
//  (4) Parity-split stream (lane = (p = wn&1, j)): e = e0 + p + 2n is linear,
//      k = k0 + 2n wraps 768 at most once (span 294), and every warp load is
//      one aligned 128B line.
//  (5) Weights swizzled in smem (idx = k + (k>>5)): conflict-free.

#define BATCH   512
#define HW      224
#define PATCH   16
#define NROWS   196
#define KLEN    768
#define NITER   147              // e-steps per thread (half-stream, one parity)
#define BAND_STRIDE 3584         // 16*224 floats per (c,hn) band
#define HALF_OFF    75264        // float offset of e-half g=1 (c=1,hn=7,wn=0)
#define IMG_ELEMS   150528       // 3*224*224
#define SWSZ    792              // 768 + 768/32 swizzle padding
#define TPB     256

__global__ __launch_bounds__(TPB, 6)
void patch_scorer_kernel(const float* __restrict__ x,
                         const float* __restrict__ W,
                         const float* __restrict__ bias,
                         float* __restrict__ out)
{
    __shared__ float sWs[SWSZ];      // swizzled weights: sWs[k + (k>>5)] = W[k]
    __shared__ float sAcc[NROWS];

    const int tid = threadIdx.x;     // 256
    const int b   = blockIdx.x >> 1; // image
    const int g   = blockIdx.x & 1;  // e-half

    #pragma unroll
    for (int k = tid; k < KLEN; k += TPB)
        sWs[k + (k >> 5)] = W[k];
    if (tid < NROWS) sAcc[tid] = 0.0f;
    __syncthreads();

    // tid = [im:3][p:1][j:4] -> warp (tid>>5) has fixed im, lanes span (p,j)
    const int im = tid >> 5;         // i mod 8  (warp id)
    const int p  = (tid >> 4) & 1;   // wn parity
    const int j  = tid & 15;         // patch column

    const int t0 = im * 16 + j;      // representative t (second member t0+128)
    const int f0 = t0 * 588 + g * 294 + p;
    const int r0 = f0 / KLEN;        // base output row
    const int k0 = f0 - r0 * KLEN;
    int n1 = (KLEN - k0 + 1) >> 1;   // steps before k wraps 768
    if (n1 > NITER) n1 = NITER;

    // warp lanes cover cols 32s + (16p + j): one aligned 128B line per load
    const float* px = x + (size_t)b * IMG_ELEMS + im * HW + p * PATCH + j
                        + g * HALF_OFF;

    float a0 = 0.f, a1 = 0.f;
    int k = k0, off = 0, s = 0, n = 0;

    #pragma unroll 7
    for (; n < n1; ++n) {
        const float w = sWs[k + (k >> 5)];
        const float* q = px + off;
        a0 += q[0]      * w;         // row i = im
        a1 += q[8 * HW] * w;         // row i = im + 8
        k += 2;
        off += 32;
        if (++s == 7) { s = 0; off += BAND_STRIDE - 7 * 32; }
    }

    atomicAdd(&sAcc[r0     ], a0);
    atomicAdd(&sAcc[r0 + 98], a1);

    if (n1 < NITER) {                // stream wraps into next output row
        k -= KLEN;                   // now 0 or 1
        a0 = a1 = 0.f;
        #pragma unroll 7
        for (; n < NITER; ++n) {
            const float w = sWs[k + (k >> 5)];
            const float* q = px + off;
            a0 += q[0]      * w;
            a1 += q[8 * HW] * w;
            k += 2;
            off += 32;
            if (++s == 7) { s = 0; off += BAND_STRIDE - 7 * 32; }
        }
        atomicAdd(&sAcc[r0 +  1], a0);
        atomicAdd(&sAcc[r0 + 99], a1);
    }

    __syncthreads();

    // two CTAs contribute to each image: combine via global atomics.
    // out is poisoned, so CTA g=0 stores (bias + its part), g=1 atomically adds.
    if (tid < NROWS) {
        if (g == 0) {
            // ordering between the two CTAs of an image is not guaranteed,
            // so both use atomicAdd onto a zeroed-by-g0 base: instead, split
            // deterministically: g0 writes its value+bias with plain store is
            // unsafe. Use atomicAdd with a one-time init by g0 via atomicExch
            // is also racy. Simplest safe: both atomicAdd, bias added by g0.
        }
    }
    // Safe combine: g==0 CTA does atomicExch-free init? Not possible without
    // ordering. Instead: both CTAs atomicAdd partial sums into out, and the
    // bias is folded in by having g==0 add (bias) once. out must start at 0:
    // harness poisons it, so we cannot rely on that. Use a __device__ global
    // scratch accumulator instead, zeroed... requires another sync. Simplest:
    // have g==0 CTA write (its + bias) non-atomically is racy with g==1 add.
    //
    // Resolution implemented below: a __device__ float scratch array holds
    // g==1 partials; g==1 CTA writes its partial there (plain store), then
    // signals via atomicAdd on a flag; g==0 CTA spins... too complex & not
    // graph-friendly. FINAL choice: dedicated second kernel combines.
    if (tid < NROWS) {
        extern __device__ float g_partial[];  // fwd decl (defined below)
        g_partial[((size_t)b * 2 + g) * NROWS + tid] = sAcc[tid];
    }
}

__device__ float g_partial[BATCH * 2 * NROWS];

__global__ __launch_bounds__(256, 8)
void combine_kernel(const float* __restrict__ bias, float* __restrict__ out)
{
    const int idx = blockIdx.x * 256 + threadIdx.x;   // over 512*196
    if (idx < BATCH * NROWS) {
        const int b = idx / NROWS;
        const int r = idx - b * NROWS;
        out[idx] = g_partial[((size_t)b * 2 + 0) * NROWS + r]
                 + g_partial[((size_t)b * 2 + 1) * NROWS + r]
                 + bias[0];
    }
}

extern "C" void kernel_launch(void* const* d_in, const int* in_sizes, int n_in,
                              void* d_out, int out_size)
{
    const float* x  = (const float*)d_in[0];   // (512,3,224,224)
    const float* W  = (const float*)d_in[1];   // (1,768)
    const float* bv = (const float*)d_in[2];   // (1,)
    float* out = (float*)d_out;                // (512,196)

    patch_scorer_kernel<<<BATCH * 2, TPB>>>(x, W, bv, out);
    combine_kernel<<<(BATCH * NROWS + 255) / 256, 256>>>(bv, out);
}

// round 7
// speedup vs baseline: 6.6122x; 2.5422x over previous
#include <cuda_runtime.h>
#include <cuda_bf16.h>

// SimplePatchScorer: x (512,3,224,224) f32, W (1,768) f32, b (1,) f32
// out (512,196) f32.
//
// f = t*588 + e, t = i*16+j, e = c*196+hn*14+wn = band*14 + wn (bands are
// contiguous 3584-float blocks). row = f/768, k = f mod 768.
//
// R7 changes (wall at 2.25 TB/s was invariant to occupancy/frontiers/L1 ->
// suspect scalar 32-bit LDG path; go wide):
//  (1) LDG.128 via float4 + __ldcs (read-once data, evict-first).
//  (2) Doubled weight array: k = kappa_t + e with kappa_t = 588t mod 768,
//      sW2[a] = W[a mod 768] (a < 1536) -> no mod in loop. Output row is
//      T_t + (kappa_t + e >= 768): predicated dual-accumulator FMA.
//  (3) Thread = (q = e-quarter, i, j' = float4 group); each float4 element m
//      has its own (kappa, T) for t = i*16 + 4j' + m.
//  (4) Weights swizzled in smem idx = a + (a>>5); broadcast pairs + swizzle
//      keep conflicts low. sAcc padded to 200 so hi-row atomics (zero when
//      no wrap) never go out of bounds.

#define BATCH   512
#define NROWS   196
#define KLEN    768
#define IMG_ELEMS  150528        // 3*224*224
#define IMG_F4     (IMG_ELEMS/4) // 37632
#define SW2SZ   1584             // 1536 + 1536/32
#define TPB     256

__global__ __launch_bounds__(TPB, 4)
void patch_scorer_kernel(const float* __restrict__ x,
                         const float* __restrict__ W,
                         const float* __restrict__ bias,
                         float* __restrict__ out)
{
    __shared__ float sW2s[SW2SZ];    // doubled + swizzled weights
    __shared__ float sAcc[200];      // 196 rows + padding for zero hi-adds

    const int tid = threadIdx.x;
    const int b   = blockIdx.x;      // image

    #pragma unroll
    for (int a = tid; a < 2 * KLEN; a += TPB) {
        const int k = (a < KLEN) ? a : a - KLEN;
        sW2s[a + (a >> 5)] = W[k];
    }
    if (tid < 200) sAcc[tid] = 0.0f;
    __syncthreads();

    const int q  = tid >> 6;         // e-quarter 0..3
    const int i  = (tid >> 2) & 15;  // patch row 0..15
    const int jp = tid & 3;          // float4 group (j = 4jp..4jp+3)

    // per-sub-element constants: t_m = i*16 + 4jp + m
    int T0, T1, T2, T3, ka0, ka1, ka2, ka3;
    {
        const int tb = i * 16 + jp * 4;
        T0 = (tb       * 588) / KLEN;  ka0 = (tb    ) * 588 - T0 * KLEN;
        T1 = ((tb + 1) * 588) / KLEN;  ka1 = (tb + 1) * 588 - T1 * KLEN;
        T2 = ((tb + 2) * 588) / KLEN;  ka2 = (tb + 2) * 588 - T2 * KLEN;
        T3 = ((tb + 3) * 588) / KLEN;  ka3 = (tb + 3) * 588 - T3 * KLEN;
    }

    const int e0   = q * 147;
    const int beta = e0 / 14;        // starting band
    int       wn   = e0 - beta * 14;

    const float4* px = (const float4*)x + (size_t)b * IMG_F4 + i * 56 + jp;
    int off = beta * 896 + wn * 4;   // float4 offset within image

    int a0 = ka0 + e0, a1 = ka1 + e0, a2 = ka2 + e0, a3 = ka3 + e0;
    float l0 = 0.f, h0 = 0.f, l1 = 0.f, h1 = 0.f;
    float l2 = 0.f, h2 = 0.f, l3 = 0.f, h3 = 0.f;

    #pragma unroll 7
    for (int n = 0; n < 147; ++n) {
        const float4 v = __ldcs(&px[off]);

        const float w0 = sW2s[a0 + (a0 >> 5)];
        const float w1 = sW2s[a1 + (a1 >> 5)];
        const float w2 = sW2s[a2 + (a2 >> 5)];
        const float w3 = sW2s[a3 + (a3 >> 5)];

        if (a0 < KLEN) l0 += v.x * w0; else h0 += v.x * w0;
        if (a1 < KLEN) l1 += v.y * w1; else h1 += v.y * w1;
        if (a2 < KLEN) l2 += v.z * w2; else h2 += v.z * w2;
        if (a3 < KLEN) l3 += v.w * w3; else h3 += v.w * w3;

        ++a0; ++a1; ++a2; ++a3;
        off += 4;
        if (++wn == 14) { wn = 0; off += 840; }   // next band
    }

    atomicAdd(&sAcc[T0    ], l0);
    atomicAdd(&sAcc[T0 + 1], h0);
    atomicAdd(&sAcc[T1    ], l1);
    atomicAdd(&sAcc[T1 + 1], h1);
    atomicAdd(&sAcc[T2    ], l2);
    atomicAdd(&sAcc[T2 + 1], h2);
    atomicAdd(&sAcc[T3    ], l3);
    atomicAdd(&sAcc[T3 + 1], h3);

    __syncthreads();

    if (tid < NROWS)
        out[(size_t)b * NROWS + tid] = sAcc[tid] + bias[0];
}

extern "C" void kernel_launch(void* const* d_in, const int* in_sizes, int n_in,
                              void* d_out, int out_size)
{
    const float* x  = (const float*)d_in[0];   // (512,3,224,224)
    const float* W  = (const float*)d_in[1];   // (1,768)
    const float* bv = (const float*)d_in[2];   // (1,)
    float* out = (float*)d_out;                // (512,196)

    patch_scorer_kernel<<<BATCH, TPB>>>(x, W, bv, out);
}